// round 1
// baseline (speedup 1.0000x reference)
#include <cuda_runtime.h>
#include <cstdint>

// Problem constants (fixed shapes)
#define BB   512
#define NN   100
#define CC   256
#define KK   3
#define NJ   103      // N + K
#define DYW  104      // sDy row stride (floats), col 103 = pad
#define KC   32       // k-chunk for GEMM1
#define WCOLS 128     // padded W chunk width

// ---------- packed f32x2 helpers (sm_103a; ptxas never auto-fuses these) ----
__device__ __forceinline__ uint64_t pack2(float s) {
    uint64_t r;
    asm("mov.b64 %0, {%1, %1};" : "=l"(r) : "r"(__float_as_uint(s)));
    return r;
}
__device__ __forceinline__ void ffma2(uint64_t& d, uint64_t a, uint64_t b) {
    asm("fma.rn.f32x2 %0, %1, %2, %0;" : "+l"(d) : "l"(a), "l"(b));
}

__global__ void __launch_bounds__(256, 1)
dysepconv_fused_kernel(const float* __restrict__ gq,
                       const float* __restrict__ gv,
                       const float* __restrict__ gW,
                       const float* __restrict__ gbias,
                       const float* __restrict__ ggamma,
                       const float* __restrict__ gbeta,
                       float* __restrict__ gout)
{
    extern __shared__ float smem[];
    // layout (floats):
    float* sDy    = smem;                      // 104 x 104   (rows 100..103 scratch)
    float* sDepth = sDy + 104 * DYW;           // 100 x 256   (later reused as sOut)
    float* sQc    = sDepth + NN * CC;          // 104 x 32    (k-chunk of q)
    float* sWc    = sQc + 104 * KC;            // 32 x 128    (k-chunk of W, padded)
    float* sBias  = sWc + KC * WCOLS;          // 128

    const int tid  = threadIdx.x;
    const int lane = tid & 31;
    const int wid  = tid >> 5;
    const int b    = blockIdx.x;

    const float* q    = gq + (size_t)b * NN * CC;
    const float* v    = gv + (size_t)b * NN * CC;
    float*       outp = gout + (size_t)b * NN * CC;

    // bias -> smem (pad to 128 with zeros)
    if (tid < 128) sBias[tid] = (tid < NJ) ? gbias[tid] : 0.0f;
    __syncthreads();

    // =========================================================
    // Stage 1: dy = q @ W + bias     (100x256 @ 256x103 -> 100x104)
    // thread (wid, lane): rows r0..r0+12, col pairs {2*lane, 64+2*lane}
    // =========================================================
    const int r0 = wid * 13;
    uint64_t acc0[13], acc1[13];
    {
        uint64_t b0 = *(const uint64_t*)&sBias[2 * lane];
        uint64_t b1 = *(const uint64_t*)&sBias[64 + 2 * lane];
        #pragma unroll
        for (int i = 0; i < 13; i++) { acc0[i] = b0; acc1[i] = b1; }
    }

    for (int kc = 0; kc < CC; kc += KC) {
        // load q chunk: 100 rows x 32 cols (800 float4)
        #pragma unroll
        for (int it = 0; it < 4; it++) {
            int idx = tid + it * 256;
            if (idx < 800) {
                int r = idx >> 3, g = idx & 7;
                *(float4*)&sQc[r * KC + g * 4] =
                    *(const float4*)&q[r * CC + kc + g * 4];
            }
        }
        // load W chunk: 32 rows x 128 cols (cols >=103 zero)
        #pragma unroll
        for (int it = 0; it < 16; it++) {
            int idx = tid + it * 256;
            int k = idx >> 7, j = idx & 127;
            sWc[idx] = (j < NJ) ? gW[(kc + k) * NJ + j] : 0.0f;
        }
        __syncthreads();

        #pragma unroll 4
        for (int k = 0; k < KC; k++) {
            uint64_t w0 = *(const uint64_t*)&sWc[k * WCOLS + 2 * lane];
            uint64_t w1 = *(const uint64_t*)&sWc[k * WCOLS + 64 + 2 * lane];
            #pragma unroll
            for (int i = 0; i < 13; i++) {
                uint64_t qp = pack2(sQc[(r0 + i) * KC + k]);
                ffma2(acc0[i], qp, w0);
                ffma2(acc1[i], qp, w1);
            }
        }
        __syncthreads();
    }

    // store dy (rows up to 103 are scratch; cols: pair0 -> 0..63, pair1(lane<20) -> 64..103)
    #pragma unroll
    for (int i = 0; i < 13; i++) {
        *(uint64_t*)&sDy[(r0 + i) * DYW + 2 * lane] = acc0[i];
        if (lane < 20)
            *(uint64_t*)&sDy[(r0 + i) * DYW + 64 + 2 * lane] = acc1[i];
    }
    __syncthreads();

    // =========================================================
    // Stage 2: depth[m][c] = relu(dw0*v[c-1] + dw1*v[c] + dw2*v[c+1])
    // dw = dy[:, 0:3]; 100x64 float4 groups = 6400 = 25 * 256
    // =========================================================
    #pragma unroll 1
    for (int it = 0; it < 25; it++) {
        int idx = tid + it * 256;
        int r = idx >> 6, g = idx & 63;
        int c0 = g * 4;
        const float* vr = v + r * CC;
        float4 vv = *(const float4*)&vr[c0];
        float vl = (c0 > 0)   ? vr[c0 - 1] : 0.0f;
        float vh = (c0 < 252) ? vr[c0 + 4] : 0.0f;
        float d0 = sDy[r * DYW + 0];
        float d1 = sDy[r * DYW + 1];
        float d2 = sDy[r * DYW + 2];
        float4 o;
        o.x = fmaxf(d0 * vl   + d1 * vv.x + d2 * vv.y, 0.0f);
        o.y = fmaxf(d0 * vv.x + d1 * vv.y + d2 * vv.z, 0.0f);
        o.z = fmaxf(d0 * vv.y + d1 * vv.z + d2 * vv.w, 0.0f);
        o.w = fmaxf(d0 * vv.z + d1 * vv.w + d2 * vh,   0.0f);
        *(float4*)&sDepth[r * CC + c0] = o;
    }
    __syncthreads();

    // =========================================================
    // Stage 3: out[n][c] = sum_m pw[n][m] * depth[m][c], pw[n][m] = dy[n][3+m]
    // thread: rows r0..r0+12, col pairs {2*lane + 64*j}, j = 0..3
    // =========================================================
    uint64_t acc[13][4];
    #pragma unroll
    for (int i = 0; i < 13; i++)
        #pragma unroll
        for (int j = 0; j < 4; j++) acc[i][j] = 0ull;

    #pragma unroll 2
    for (int m = 0; m < NN; m++) {
        uint64_t dp0 = *(const uint64_t*)&sDepth[m * CC +       2 * lane];
        uint64_t dp1 = *(const uint64_t*)&sDepth[m * CC +  64 + 2 * lane];
        uint64_t dp2 = *(const uint64_t*)&sDepth[m * CC + 128 + 2 * lane];
        uint64_t dp3 = *(const uint64_t*)&sDepth[m * CC + 192 + 2 * lane];
        #pragma unroll
        for (int i = 0; i < 13; i++) {
            uint64_t pp = pack2(sDy[(r0 + i) * DYW + KK + m]);
            ffma2(acc[i][0], pp, dp0);
            ffma2(acc[i][1], pp, dp1);
            ffma2(acc[i][2], pp, dp2);
            ffma2(acc[i][3], pp, dp3);
        }
    }
    __syncthreads();   // all reads of sDepth complete

    // store pre-LN result into sDepth (reuse as sOut), guarded to real rows
    #pragma unroll
    for (int i = 0; i < 13; i++) {
        int r = r0 + i;
        if (r < NN) {
            *(uint64_t*)&sDepth[r * CC +       2 * lane] = acc[i][0];
            *(uint64_t*)&sDepth[r * CC +  64 + 2 * lane] = acc[i][1];
            *(uint64_t*)&sDepth[r * CC + 128 + 2 * lane] = acc[i][2];
            *(uint64_t*)&sDepth[r * CC + 192 + 2 * lane] = acc[i][3];
        }
    }
    __syncthreads();

    // =========================================================
    // Stage 4: LayerNorm over C per row; warp per row
    // =========================================================
    float4 g0 = *(const float4*)&ggamma[lane * 4];
    float4 g1 = *(const float4*)&ggamma[128 + lane * 4];
    float4 be0 = *(const float4*)&gbeta[lane * 4];
    float4 be1 = *(const float4*)&gbeta[128 + lane * 4];

    for (int r = wid; r < NN; r += 8) {
        float4 x0 = *(const float4*)&sDepth[r * CC + lane * 4];
        float4 x1 = *(const float4*)&sDepth[r * CC + 128 + lane * 4];
        float s  = x0.x + x0.y + x0.z + x0.w + x1.x + x1.y + x1.z + x1.w;
        float ss = x0.x*x0.x + x0.y*x0.y + x0.z*x0.z + x0.w*x0.w
                 + x1.x*x1.x + x1.y*x1.y + x1.z*x1.z + x1.w*x1.w;
        #pragma unroll
        for (int off = 16; off >= 1; off >>= 1) {
            s  += __shfl_xor_sync(0xffffffffu, s,  off);
            ss += __shfl_xor_sync(0xffffffffu, ss, off);
        }
        float mu  = s * (1.0f / 256.0f);
        float var = ss * (1.0f / 256.0f) - mu * mu;
        float inv = rsqrtf(var + 1e-5f);
        float4 o0, o1;
        o0.x = (x0.x - mu) * inv * g0.x + be0.x;
        o0.y = (x0.y - mu) * inv * g0.y + be0.y;
        o0.z = (x0.z - mu) * inv * g0.z + be0.z;
        o0.w = (x0.w - mu) * inv * g0.w + be0.w;
        o1.x = (x1.x - mu) * inv * g1.x + be1.x;
        o1.y = (x1.y - mu) * inv * g1.y + be1.y;
        o1.z = (x1.z - mu) * inv * g1.z + be1.z;
        o1.w = (x1.w - mu) * inv * g1.w + be1.w;
        *(float4*)&outp[r * CC + lane * 4] = o0;
        *(float4*)&outp[r * CC + 128 + lane * 4] = o1;
    }
}

extern "C" void kernel_launch(void* const* d_in, const int* in_sizes, int n_in,
                              void* d_out, int out_size) {
    const float* q     = (const float*)d_in[0];
    const float* v     = (const float*)d_in[1];
    const float* W     = (const float*)d_in[2];
    const float* bias  = (const float*)d_in[3];
    const float* gamma = (const float*)d_in[4];
    const float* beta  = (const float*)d_in[5];
    float* out = (float*)d_out;

    const int smem_bytes = (104 * DYW + NN * CC + 104 * KC + KC * WCOLS + 128)
                           * (int)sizeof(float);   // ~172 KB
    cudaFuncSetAttribute(dysepconv_fused_kernel,
                         cudaFuncAttributeMaxDynamicSharedMemorySize, smem_bytes);
    dysepconv_fused_kernel<<<BB, 256, smem_bytes>>>(q, v, W, bias, gamma, beta, out);
}